// round 8
// baseline (speedup 1.0000x reference)
#include <cuda_runtime.h>
#include <cuda_bf16.h>
#include <cstdint>
#include <cstdio>

// Shapes (fixed per reference): B=4, T=1024, S=32, D=512
#define BT    4096
#define DIM   512
#define DIM2  1024
#define SLOTS 32

// Scratch (device globals; referenced ONLY inside device code)
__device__ float g_Q [BT * DIM];
__device__ float g_Qk[BT * DIM2];
__device__ float g_wH[BT * DIM2];

// ---------------------------------------------------------------------------
// Touch test A: write first/last element of d_out interpreted as out_size
// float32 elements (both overwritten later by gemm4 -> deterministic).
// ---------------------------------------------------------------------------
__global__ void touchA_k(float* out, long long outElems)
{
    if (threadIdx.x == 0) {
        out[0] = 0.f;
        out[outElems - 1] = 0.f;
    }
}

// ---------------------------------------------------------------------------
// Scalar SGEMM (fp32 inputs proven): 64x64 tile, 256 threads, 4x4 micro-tile.
// ASRC: 1 = concat(A=cur_r, A2=cur_i) rows of 512+512; 2 = g_Q; 3 = g_wH
// BMODE: 0 = B row-major [K x *] with row stride Bstride (use cols 0..N-1)
//        1 = B is [N x K] (use B^T), row stride K
// EPI: 0 = C[m*N+n] = (acc + bias?[n]) * (rowscale? basescale*rowscale[m] : 1)
//      1 = real-residual epilogue: C[m*512+n] = cur_r[m*512+n] + 0.1*(acc+bias[n])
// CDST: 0 = g_Q, 1 = g_Qk, 2 = external C (write-guarded by Cn)
// ---------------------------------------------------------------------------
template<int ASRC, int BMODE, int EPI, int CDST>
__global__ __launch_bounds__(256)
void gemm_s(const float* __restrict__ A, const float* __restrict__ A2,
            const float* __restrict__ B, int Bstride,
            const float* __restrict__ bias,
            const float* __restrict__ rowscale, float basescale,
            const float* __restrict__ cur_r,
            float* __restrict__ Cext, long long Cn,
            int M, int N, int K)
{
    __shared__ float As[16][65];
    __shared__ float Bs[16][65];

    const float* Aint = (ASRC == 2) ? g_Q : (ASRC == 3) ? g_wH : nullptr;
    float*       C    = (CDST == 0) ? g_Q : (CDST == 1) ? g_Qk : Cext;

    const int tid = threadIdx.x;
    const int tx  = tid & 15;
    const int ty  = tid >> 4;
    const int bm  = blockIdx.y * 64;
    const int bn  = blockIdx.x * 64;

    float acc[4][4];
#pragma unroll
    for (int i = 0; i < 4; i++)
#pragma unroll
        for (int j = 0; j < 4; j++) acc[i][j] = 0.f;

    for (int k0 = 0; k0 < K; k0 += 16) {
        // A tile: 64 rows x 16 k
#pragma unroll
        for (int i = 0; i < 4; i++) {
            const int idx = tid + i * 256;
            const int row = idx >> 4;
            const int kk  = idx & 15;
            const long long m = bm + row;
            const long long k = k0 + kk;
            float v;
            if (ASRC == 1) {
                v = (k < 512) ? __ldg(A  + m * 512 + k)
                              : __ldg(A2 + m * 512 + (k - 512));
            } else {
                v = Aint[m * (long long)K + k];
            }
            As[kk][row] = v;
        }
        // B tile: 16 k x 64 n
#pragma unroll
        for (int i = 0; i < 4; i++) {
            const int idx = tid + i * 256;
            if (BMODE == 0) {
                const int kk = idx >> 6;
                const int n  = idx & 63;
                Bs[kk][n] = __ldg(B + (long long)(k0 + kk) * Bstride + (bn + n));
            } else {
                const int n  = idx >> 4;
                const int kk = idx & 15;
                Bs[kk][n] = __ldg(B + (long long)(bn + n) * K + (k0 + kk));
            }
        }
        __syncthreads();

#pragma unroll
        for (int kk = 0; kk < 16; kk++) {
            float a0 = As[kk][ty * 4 + 0];
            float a1 = As[kk][ty * 4 + 1];
            float a2 = As[kk][ty * 4 + 2];
            float a3 = As[kk][ty * 4 + 3];
            float b0 = Bs[kk][tx * 4 + 0];
            float b1 = Bs[kk][tx * 4 + 1];
            float b2 = Bs[kk][tx * 4 + 2];
            float b3 = Bs[kk][tx * 4 + 3];
            acc[0][0] = fmaf(a0, b0, acc[0][0]);
            acc[0][1] = fmaf(a0, b1, acc[0][1]);
            acc[0][2] = fmaf(a0, b2, acc[0][2]);
            acc[0][3] = fmaf(a0, b3, acc[0][3]);
            acc[1][0] = fmaf(a1, b0, acc[1][0]);
            acc[1][1] = fmaf(a1, b1, acc[1][1]);
            acc[1][2] = fmaf(a1, b2, acc[1][2]);
            acc[1][3] = fmaf(a1, b3, acc[1][3]);
            acc[2][0] = fmaf(a2, b0, acc[2][0]);
            acc[2][1] = fmaf(a2, b1, acc[2][1]);
            acc[2][2] = fmaf(a2, b2, acc[2][2]);
            acc[2][3] = fmaf(a2, b3, acc[2][3]);
            acc[3][0] = fmaf(a3, b0, acc[3][0]);
            acc[3][1] = fmaf(a3, b1, acc[3][1]);
            acc[3][2] = fmaf(a3, b2, acc[3][2]);
            acc[3][3] = fmaf(a3, b3, acc[3][3]);
        }
        __syncthreads();
    }

#pragma unroll
    for (int i = 0; i < 4; i++) {
        const long long m = bm + ty * 4 + i;
        float rs = 1.f;
        if (EPI == 0 && rowscale != nullptr)
            rs = basescale * __ldg(rowscale + m);
#pragma unroll
        for (int j = 0; j < 4; j++) {
            const long long n = bn + tx * 4 + j;
            float v = acc[i][j];
            if (bias != nullptr) v += __ldg(bias + n);
            if (EPI == 0) {
                C[m * N + n] = v * rs;
            } else {
                const long long f = m * 512 + n;
                const float r = __ldg(cur_r + f);
                if (f >= 0 && f < Cn) C[f] = r + 0.1f * v;
            }
        }
    }
}

// ---------------------------------------------------------------------------
// Streaming attention: per (b,t) CTA (256 thr). One pass over H (32 x 1024)
// with online softmax; accumulates wH = sum_s w_s * H_s into g_wH.
// ---------------------------------------------------------------------------
__global__ __launch_bounds__(256)
void attn_s(const float* __restrict__ hr, const float* __restrict__ hi)
{
    const int bt   = blockIdx.x;
    const int tid  = threadIdx.x;
    const int lane = tid & 31;
    const int wid  = tid >> 5;
    __shared__ float red[2][8];

    const int j = tid * 4;
    const bool isr = (j < 512);
    const float* src = isr ? hr : hi;
    const long long base = (long long)bt * (SLOTS * 512) + (isr ? j : j - 512);

    const long long qb0 = (long long)bt * DIM2 + j;
    const float q0 = g_Qk[qb0 + 0];
    const float q1 = g_Qk[qb0 + 1];
    const float q2 = g_Qk[qb0 + 2];
    const float q3 = g_Qk[qb0 + 3];

    float m = -1e30f, l = 0.f;
    float a0 = 0.f, a1 = 0.f, a2 = 0.f, a3 = 0.f;

#pragma unroll 1
    for (int s = 0; s < SLOTS; s++) {
        const long long o = base + (long long)s * 512;
        const float h0 = __ldg(src + o + 0);
        const float h1 = __ldg(src + o + 1);
        const float h2 = __ldg(src + o + 2);
        const float h3 = __ldg(src + o + 3);

        float p = h0 * q0 + h1 * q1 + h2 * q2 + h3 * q3;
#pragma unroll
        for (int off = 16; off; off >>= 1)
            p += __shfl_xor_sync(0xffffffffu, p, off);
        if (lane == 0) red[s & 1][wid] = p;
        __syncthreads();
        float score = 0.f;
#pragma unroll
        for (int w = 0; w < 8; w++) score += red[s & 1][w];

        const float mn = fmaxf(m, score);
        const float cf = __expf(m - mn);
        const float pw = __expf(score - mn);
        l  = l  * cf + pw;
        a0 = a0 * cf + pw * h0;
        a1 = a1 * cf + pw * h1;
        a2 = a2 * cf + pw * h2;
        a3 = a3 * cf + pw * h3;
        m = mn;
    }
    const float inv = 1.f / l;
    const long long w0 = (long long)bt * DIM2 + j;
    g_wH[w0 + 0] = a0 * inv;
    g_wH[w0 + 1] = a1 * inv;
    g_wH[w0 + 2] = a2 * inv;
    g_wH[w0 + 3] = a3 * inv;
}

// ---------------------------------------------------------------------------
// Host-side diagnostics (active ONLY when not graph-capturing).
// ---------------------------------------------------------------------------
static bool kl_capturing()
{
    cudaStreamCaptureStatus st = cudaStreamCaptureStatusNone;
    cudaError_t e = cudaStreamIsCapturing((cudaStream_t)0, &st);
    if (e != cudaSuccess) { (void)cudaGetLastError(); return true; }
    return st != cudaStreamCaptureStatusNone;
}

static cudaError_t kl_poll()
{
    cudaEvent_t ev;
    if (cudaEventCreateWithFlags(&ev, cudaEventDisableTiming) != cudaSuccess)
        return cudaGetLastError();
    cudaEventRecord(ev, (cudaStream_t)0);
    cudaError_t e;
    do { e = cudaEventQuery(ev); } while (e == cudaErrorNotReady);
    cudaEventDestroy(ev);
    return e;
}

static void kl_stage(bool diag, const char* name, bool* dead)
{
    if (!diag || *dead) return;
    cudaError_t e = kl_poll();
    fprintf(stderr, "[KLDIAG] stage %-8s -> %s\n", name, cudaGetErrorString(e));
    if (e != cudaSuccess) *dead = true;
}

// ---------------------------------------------------------------------------
extern "C" void kernel_launch(void* const* d_in, const int* in_sizes, int n_in,
                              void* d_out, int out_size)
{
    const bool diag = !kl_capturing();

    // Input order CONFIRMED (R7 diagnostics): insertion order, all fp32.
    // 0=hist_real 1=hist_imag 2=cur_r 3=cur_i 4=conf 5=qW 6=qb 7=kW 8=kb 9=vW 10=vb
    if (n_in < 11) { if (diag) fprintf(stderr, "[KLDIAG] n_in=%d\n", n_in); return; }
    const float* hr   = (const float*)d_in[0];
    const float* hi   = (const float*)d_in[1];
    const float* cr   = (const float*)d_in[2];
    const float* ci   = (const float*)d_in[3];
    const float* conf = (const float*)d_in[4];
    const float* qW   = (const float*)d_in[5];
    const float* qb   = (const float*)d_in[6];
    const float* kW   = (const float*)d_in[7];
    // d_in[8] = kb: softmax-invariant constant, unused
    const float* vW   = (const float*)d_in[9];
    const float* vb   = (const float*)d_in[10];
    float* out = (float*)d_out;

    // CONFIRMED (R7): d_out holds out_size (=2097152) elements of <=4 bytes.
    // Treat as float32 real-part output: out[m*512+d] = real(result).
    const long long outElems = (long long)out_size;

    const float scale = 0.044194173824159216f;   // 512^-0.5
    bool dead = false;

    // S0: output extent touch (overwritten by gemm4)
    touchA_k<<<1, 32>>>(out, outElems);
    kl_stage(diag, "touchA", &dead);
    if (dead) return;

    // S1: Q = concat(cur_r,cur_i) @ qW + qb -> g_Q       [4096,512], K=1024
    gemm_s<1, 0, 0, 0><<<dim3(DIM / 64, BT / 64), 256>>>(
        cr, ci, qW, DIM, qb, nullptr, 1.f, nullptr, nullptr, 0, BT, DIM, DIM2);
    kl_stage(diag, "gemm1", &dead);
    if (dead) return;

    // S2: Qk' = (Q @ kW^T) * scale * conf[row] -> g_Qk   [4096,1024], K=512
    gemm_s<2, 1, 0, 1><<<dim3(DIM2 / 64, BT / 64), 256>>>(
        nullptr, nullptr, kW, 0, nullptr, conf, scale, nullptr, nullptr, 0,
        BT, DIM2, DIM);
    kl_stage(diag, "gemm2", &dead);
    if (dead) return;

    // S3: streaming online-softmax over S=32 -> g_wH
    attn_s<<<BT, 256>>>(hr, hi);
    kl_stage(diag, "attn", &dead);
    if (dead) return;

    // S4: out = cur_r + 0.1 * (wH @ vW[:,0:512] + vb[0:512])  (REAL part only)
    gemm_s<3, 0, 1, 2><<<dim3(DIM / 64, BT / 64), 256>>>(
        nullptr, nullptr, vW, DIM2, vb, nullptr, 1.f, cr, out, outElems,
        BT, DIM, DIM2);
    kl_stage(diag, "gemm4", &dead);
}

// round 9
// speedup vs baseline: 1.2602x; 1.2602x over previous
#include <cuda_runtime.h>
#include <cuda_bf16.h>
#include <cstdint>
#include <cstdio>

// Shapes (confirmed R7/R8): B=4, T=1024, S=32, D=512; output = real part, fp32.
#define BT    4096
#define DIM   512
#define DIM2  1024
#define SLOTS 32

__device__ float g_Q [BT * DIM];
__device__ float g_Qk[BT * DIM2];
__device__ float g_wH[BT * DIM2];

// ---- packed fp32x2 helpers (sm_103a FFMA2 path) ----------------------------
__device__ __forceinline__ unsigned long long pk2(float x, float y)
{
    unsigned long long r;
    asm("mov.b64 %0, {%1, %2};"
        : "=l"(r) : "r"(__float_as_uint(x)), "r"(__float_as_uint(y)));
    return r;
}
__device__ __forceinline__ unsigned long long ffma2(unsigned long long a,
                                                    unsigned long long b,
                                                    unsigned long long c)
{
    unsigned long long d;
    asm("fma.rn.f32x2 %0, %1, %2, %3;" : "=l"(d) : "l"(a), "l"(b), "l"(c));
    return d;
}
__device__ __forceinline__ float2 upk2(unsigned long long v)
{
    unsigned lo, hi;
    asm("mov.b64 {%0, %1}, %2;" : "=r"(lo), "=r"(hi) : "l"(v));
    return make_float2(__uint_as_float(lo), __uint_as_float(hi));
}

// ---------------------------------------------------------------------------
// FFMA2 SGEMM: 128x128 tile, 256 threads, 8x8 micro-tile (as 8x4 f32x2 pairs),
// K-tile 16. Exact fp32 semantics.
// ASRC: 1 = concat(A=cur_r, A2=cur_i) rows of 512+512; 2 = g_Q; 3 = g_wH
// BMODE: 0 = B row-major [K x Bstride] (cols 0..N-1); 1 = B is [N x K] (B^T)
// EPI: 0 = C[m*N+n] = (acc + bias?[n]) * (rowscale? basescale*rowscale[m] : 1)
//      1 = real epilogue: C[m*512+n] = cur_r[m*512+n] + 0.1*(acc + bias[n])
// CDST: 0 = g_Q, 1 = g_Qk, 2 = external C
// ---------------------------------------------------------------------------
template<int ASRC, int BMODE, int EPI, int CDST>
__global__ __launch_bounds__(256)
void gemm_f(const float* __restrict__ A, const float* __restrict__ A2,
            const float* __restrict__ B, int Bstride,
            const float* __restrict__ bias,
            const float* __restrict__ rowscale, float basescale,
            const float* __restrict__ cur_r,
            float* __restrict__ Cext,
            int M, int N, int K)
{
    __shared__ __align__(16) float As[16][128];
    __shared__ __align__(16) float Bs[16][128];

    const float* Aint = (ASRC == 2) ? g_Q : (ASRC == 3) ? g_wH : nullptr;
    float*       C    = (CDST == 0) ? g_Q : (CDST == 1) ? g_Qk : Cext;

    const int tid = threadIdx.x;
    const int tx  = tid & 15;
    const int ty  = tid >> 4;
    const int tm  = ty * 8;
    const int tn  = tx * 8;
    const int bm  = blockIdx.y * 128;
    const int bn  = blockIdx.x * 128;

    unsigned long long acc2[8][4];
#pragma unroll
    for (int i = 0; i < 8; i++)
#pragma unroll
        for (int j = 0; j < 4; j++) acc2[i][j] = 0ull;

    const int ar  = tid >> 2;          // 0..63 (+64)
    const int ak  = (tid & 3) * 4;     // 0,4,8,12
    const int bk0 = tid >> 5;          // 0..7 (+8)       (BMODE 0)
    const int bnc = (tid & 31) * 4;
    const int br  = tid >> 2;          // 0..63 (+64)     (BMODE 1)
    const int bkc = (tid & 3) * 4;

    for (int k0 = 0; k0 < K; k0 += 16) {
        // A tile (k-major)
#pragma unroll
        for (int h = 0; h < 2; h++) {
            const long long m = bm + ar + h * 64;
            const long long k = k0 + ak;
            float4 v;
            if (ASRC == 1) {
                v = (k < 512) ? *(const float4*)(A  + m * 512 + k)
                              : *(const float4*)(A2 + m * 512 + (k - 512));
            } else {
                v = *(const float4*)(Aint + m * (long long)K + k);
            }
            As[ak + 0][ar + h * 64] = v.x;
            As[ak + 1][ar + h * 64] = v.y;
            As[ak + 2][ar + h * 64] = v.z;
            As[ak + 3][ar + h * 64] = v.w;
        }
        // B tile
        if (BMODE == 0) {
#pragma unroll
            for (int h = 0; h < 2; h++) {
                const long long k = k0 + bk0 + h * 8;
                const float4 v = *(const float4*)(B + k * Bstride + (bn + bnc));
                Bs[bk0 + h * 8][bnc + 0] = v.x;
                Bs[bk0 + h * 8][bnc + 1] = v.y;
                Bs[bk0 + h * 8][bnc + 2] = v.z;
                Bs[bk0 + h * 8][bnc + 3] = v.w;
            }
        } else {
#pragma unroll
            for (int h = 0; h < 2; h++) {
                const long long n = bn + br + h * 64;
                const long long k = k0 + bkc;
                const float4 v = *(const float4*)(B + n * K + k);
                Bs[bkc + 0][br + h * 64] = v.x;
                Bs[bkc + 1][br + h * 64] = v.y;
                Bs[bkc + 2][br + h * 64] = v.z;
                Bs[bkc + 3][br + h * 64] = v.w;
            }
        }
        __syncthreads();

#pragma unroll
        for (int kk = 0; kk < 16; kk++) {
            const float4 a0 = *(const float4*)&As[kk][tm];
            const float4 a1 = *(const float4*)&As[kk][tm + 4];
            const float4 b0 = *(const float4*)&Bs[kk][tn];
            const float4 b1 = *(const float4*)&Bs[kk][tn + 4];
            unsigned long long bp[4];
            bp[0] = pk2(b0.x, b0.y);
            bp[1] = pk2(b0.z, b0.w);
            bp[2] = pk2(b1.x, b1.y);
            bp[3] = pk2(b1.z, b1.w);
            const float av[8] = {a0.x, a0.y, a0.z, a0.w,
                                 a1.x, a1.y, a1.z, a1.w};
#pragma unroll
            for (int i = 0; i < 8; i++) {
                const unsigned long long ad = pk2(av[i], av[i]);
#pragma unroll
                for (int j = 0; j < 4; j++)
                    acc2[i][j] = ffma2(ad, bp[j], acc2[i][j]);
            }
        }
        __syncthreads();
    }

    // epilogue
#pragma unroll
    for (int i = 0; i < 8; i++) {
        const long long m = bm + tm + i;
        float rs = 1.f;
        if (EPI == 0 && rowscale != nullptr)
            rs = basescale * __ldg(rowscale + m);
#pragma unroll
        for (int j = 0; j < 4; j++) {
            const float2 v2 = upk2(acc2[i][j]);
            const long long n0 = bn + tn + 2 * j;
            float v0 = v2.x, v1 = v2.y;
            if (bias != nullptr) {
                v0 += __ldg(bias + n0);
                v1 += __ldg(bias + n0 + 1);
            }
            if (EPI == 0) {
                C[m * N + n0]     = v0 * rs;
                C[m * N + n0 + 1] = v1 * rs;
            } else {
                const long long f = m * 512 + n0;
                C[f]     = __ldg(cur_r + f)     + 0.1f * v0;
                C[f + 1] = __ldg(cur_r + f + 1) + 0.1f * v1;
            }
        }
    }
}

// ---------------------------------------------------------------------------
// Warp-specialized streaming attention. CTA = one (b,t), 8 warps.
// Warp w handles slots {w, w+8, w+16, w+24}: per-slot score via 5 SHFLs
// (no block sync in the loop), per-warp online softmax, one final merge.
// ---------------------------------------------------------------------------
__global__ __launch_bounds__(256)
void attn_f(const float* __restrict__ hr, const float* __restrict__ hi)
{
    __shared__ __align__(16) float shQ[DIM2];
    __shared__ __align__(16) float shAcc[8][8][32][4];   // [srcWarp][chunk][lane][4]
    __shared__ float shM[8], shL[8];

    const int bt = blockIdx.x;
    const int w  = threadIdx.x >> 5;
    const int c  = threadIdx.x & 31;

    // Stage Q row (g_Qk already has d^-1/2 * conf folded in)
    {
        const float* q = g_Qk + (size_t)bt * DIM2;
#pragma unroll
        for (int i = 0; i < 1; i++) { /* keep simple: one float4 per thread */ }
        *(float4*)&shQ[threadIdx.x * 4] = *(const float4*)(q + threadIdx.x * 4);
    }
    __syncthreads();

    const float* pr = hr + (size_t)bt * (SLOTS * 512) + 4 * c;
    const float* pi = hi + (size_t)bt * (SLOTS * 512) + 4 * c;

    float m = -1e30f, l = 0.f;
    float4 acc[8];
#pragma unroll
    for (int k = 0; k < 8; k++) acc[k] = make_float4(0.f, 0.f, 0.f, 0.f);

#pragma unroll
    for (int si = 0; si < 4; si++) {
        const int s = w + si * 8;
        float4 h[8];
#pragma unroll
        for (int k = 0; k < 4; k++)
            h[k] = *(const float4*)(pr + (size_t)s * 512 + k * 128);
#pragma unroll
        for (int k = 0; k < 4; k++)
            h[k + 4] = *(const float4*)(pi + (size_t)s * 512 + k * 128);

        float p = 0.f;
#pragma unroll
        for (int k = 0; k < 8; k++) {
            const float4 q = *(const float4*)&shQ[k * 128 + 4 * c];
            p += h[k].x * q.x + h[k].y * q.y + h[k].z * q.z + h[k].w * q.w;
        }
#pragma unroll
        for (int off = 16; off; off >>= 1)
            p += __shfl_xor_sync(0xffffffffu, p, off);

        const float mn = fmaxf(m, p);
        const float cf = __expf(m - mn);
        const float pw = __expf(p - mn);
        l = l * cf + pw;
#pragma unroll
        for (int k = 0; k < 8; k++) {
            acc[k].x = acc[k].x * cf + pw * h[k].x;
            acc[k].y = acc[k].y * cf + pw * h[k].y;
            acc[k].z = acc[k].z * cf + pw * h[k].z;
            acc[k].w = acc[k].w * cf + pw * h[k].w;
        }
        m = mn;
    }

    // merge the 8 per-warp partial softmax states
    if (c == 0) { shM[w] = m; shL[w] = l; }
    __syncthreads();
    float M = -1e30f;
#pragma unroll
    for (int i = 0; i < 8; i++) M = fmaxf(M, shM[i]);
    float L = 0.f;
#pragma unroll
    for (int i = 0; i < 8; i++) L += shL[i] * __expf(shM[i] - M);
    const float myE = __expf(m - M);

#pragma unroll
    for (int k = 0; k < 8; k++) {
        float4 v = acc[k];
        v.x *= myE; v.y *= myE; v.z *= myE; v.w *= myE;
        *(float4*)&shAcc[w][k][c][0] = v;
    }
    __syncthreads();

    // thread (w,c) owns output columns [w*128 + 4c, +4)
    const float invL = 1.f / L;
    float4 sum = make_float4(0.f, 0.f, 0.f, 0.f);
#pragma unroll
    for (int sw = 0; sw < 8; sw++) {
        const float4 v = *(const float4*)&shAcc[sw][w][c][0];
        sum.x += v.x; sum.y += v.y; sum.z += v.z; sum.w += v.w;
    }
    sum.x *= invL; sum.y *= invL; sum.z *= invL; sum.w *= invL;
    *(float4*)&g_wH[(size_t)bt * DIM2 + w * 128 + 4 * c] = sum;
}

// ---------------------------------------------------------------------------
// Host-side staged diagnostics (only on the non-captured correctness call).
// ---------------------------------------------------------------------------
static bool kl_capturing()
{
    cudaStreamCaptureStatus st = cudaStreamCaptureStatusNone;
    cudaError_t e = cudaStreamIsCapturing((cudaStream_t)0, &st);
    if (e != cudaSuccess) { (void)cudaGetLastError(); return true; }
    return st != cudaStreamCaptureStatusNone;
}
static cudaError_t kl_poll()
{
    cudaEvent_t ev;
    if (cudaEventCreateWithFlags(&ev, cudaEventDisableTiming) != cudaSuccess)
        return cudaGetLastError();
    cudaEventRecord(ev, (cudaStream_t)0);
    cudaError_t e;
    do { e = cudaEventQuery(ev); } while (e == cudaErrorNotReady);
    cudaEventDestroy(ev);
    return e;
}
static void kl_stage(bool diag, const char* name, bool* dead)
{
    if (!diag || *dead) return;
    cudaError_t e = kl_poll();
    if (e != cudaSuccess) {
        fprintf(stderr, "[KLDIAG] stage %s -> %s\n", name, cudaGetErrorString(e));
        *dead = true;
    }
}

// ---------------------------------------------------------------------------
extern "C" void kernel_launch(void* const* d_in, const int* in_sizes, int n_in,
                              void* d_out, int out_size)
{
    const bool diag = !kl_capturing();
    if (n_in < 11) return;

    // Confirmed insertion order, all fp32:
    // 0=hist_real 1=hist_imag 2=cur_r 3=cur_i 4=conf 5=qW 6=qb 7=kW 8=kb 9=vW 10=vb
    const float* hr   = (const float*)d_in[0];
    const float* hi   = (const float*)d_in[1];
    const float* cr   = (const float*)d_in[2];
    const float* ci   = (const float*)d_in[3];
    const float* conf = (const float*)d_in[4];
    const float* qW   = (const float*)d_in[5];
    const float* qb   = (const float*)d_in[6];
    const float* kW   = (const float*)d_in[7];
    // d_in[8] = kb: softmax-invariant, unused
    const float* vW   = (const float*)d_in[9];
    const float* vb   = (const float*)d_in[10];
    float* out = (float*)d_out;   // out_size=2097152 fp32 = real part

    const float scale = 0.044194173824159216f;   // 512^-0.5
    bool dead = false;

    // 1) Q = concat(cur_r,cur_i) @ qW + qb -> g_Q        [4096,512], K=1024
    gemm_f<1, 0, 0, 0><<<dim3(DIM / 128, BT / 128), 256>>>(
        cr, ci, qW, DIM, qb, nullptr, 1.f, nullptr, nullptr, BT, DIM, DIM2);
    kl_stage(diag, "gemm1", &dead);
    if (dead) return;

    // 2) Qk' = (Q @ kW^T) * scale * conf[row] -> g_Qk    [4096,1024], K=512
    gemm_f<2, 1, 0, 1><<<dim3(DIM2 / 128, BT / 128), 256>>>(
        nullptr, nullptr, kW, 0, nullptr, conf, scale, nullptr, nullptr,
        BT, DIM2, DIM);
    kl_stage(diag, "gemm2", &dead);
    if (dead) return;

    // 3) warp-specialized online-softmax stream -> g_wH
    attn_f<<<BT, 256>>>(hr, hi);
    kl_stage(diag, "attn", &dead);
    if (dead) return;

    // 4) out = cur_r + 0.1 * (wH @ vW[:,0:512] + vb[0:512])   (real part)
    gemm_f<3, 0, 1, 2><<<dim3(DIM / 128, BT / 128), 256>>>(
        nullptr, nullptr, vW, DIM2, vb, nullptr, 1.f, cr, out, BT, DIM, DIM2);
    kl_stage(diag, "gemm4", &dead);
}

// round 10
// speedup vs baseline: 1.9497x; 1.5471x over previous
#include <cuda_runtime.h>
#include <cuda_bf16.h>
#include <cstdint>
#include <cstdio>

// Shapes (confirmed): B=4, T=1024, S=32, D=512; output = real part, fp32.
#define BT    4096
#define DIM   512
#define DIM2  1024
#define SLOTS 32

__device__ float g_Q [BT * DIM];
__device__ float g_Qk[BT * DIM2];
__device__ float g_wH[BT * DIM2];

__device__ __forceinline__ unsigned tf32cvt(float f)
{
    unsigned r;
    asm("cvt.rna.tf32.f32 %0, %1;" : "=r"(r) : "f"(f));
    return r;
}

// ---------------------------------------------------------------------------
// TF32 tensor-core GEMM: CTA tile 64(m) x 128(n), 256 threads (8 warps, 2x4),
// warp tile 32x32 = 2(m) x 4(n) mma.m16n8k8 tiles, K-tile 16. fp32 accumulate.
// ASRC: 1 = concat(A=cur_r, A2=cur_i) rows of 512+512; 2 = g_Q; 3 = g_wH
// BMODE: 0 = B row-major [K x Bstride] (cols bn0..bn0+127); 1 = B is [N x K]
// EPI: 0 = C[m*N+n] = (acc + bias?[n]) * (rowscale? basescale*rowscale[m] : 1)
//      1 = real epilogue: C[m*512+n] = cur_r[m*512+n] + 0.1*(acc + bias[n])
// CDST: 0 = g_Q, 1 = g_Qk, 2 = external C
// ---------------------------------------------------------------------------
template<int ASRC, int BMODE, int EPI, int CDST>
__global__ __launch_bounds__(256)
void gemm_t(const float* __restrict__ A, const float* __restrict__ A2,
            const float* __restrict__ B, int Bstride,
            const float* __restrict__ bias,
            const float* __restrict__ rowscale, float basescale,
            const float* __restrict__ cur_r,
            float* __restrict__ Cext,
            int M, int N, int K)
{
    __shared__ unsigned As[16][72];                  // [k][m], padded
    __shared__ __align__(16) unsigned Bs[16][136];   // [k][n], padded

    const float* Aint = (ASRC == 2) ? g_Q : (ASRC == 3) ? g_wH : nullptr;
    float*       C    = (CDST == 0) ? g_Q : (CDST == 1) ? g_Qk : Cext;

    const int tid  = threadIdx.x;
    const int lane = tid & 31;
    const int wid  = tid >> 5;
    const int wm   = wid & 1;        // warp row   (2)
    const int wn   = wid >> 1;       // warp col   (4)
    const int grp  = lane >> 2;      // 0..7
    const int tig  = lane & 3;       // 0..3
    const int bm   = blockIdx.y * 64;
    const int bn0  = blockIdx.x * 128;

    float acc[2][4][4];
#pragma unroll
    for (int a = 0; a < 2; a++)
#pragma unroll
        for (int b = 0; b < 4; b++)
#pragma unroll
            for (int c = 0; c < 4; c++) acc[a][b][c] = 0.f;

    const int ar  = tid >> 2;            // A loader: row 0..63
    const int ak  = (tid & 3) * 4;       // A loader: k 0,4,8,12
    const int bk  = tid >> 5;            // B loader (BMODE0): k 0..7 (+8)
    const int bnc = (tid & 31) * 4;      // B loader (BMODE0): n
    const int b1n = tid >> 1;            // B loader (BMODE1): n 0..127
    const int b1k = (tid & 1) * 8;       // B loader (BMODE1): k 0 or 8

    for (int k0 = 0; k0 < K; k0 += 16) {
        // --- A tile 64 x 16 (k-major, tf32) ---
        {
            const long long m = bm + ar;
            const long long k = k0 + ak;
            float4 v;
            if (ASRC == 1) {
                v = (k < 512) ? *(const float4*)(A  + m * 512 + k)
                              : *(const float4*)(A2 + m * 512 + (k - 512));
            } else {
                v = *(const float4*)(Aint + m * (long long)K + k);
            }
            As[ak + 0][ar] = tf32cvt(v.x);
            As[ak + 1][ar] = tf32cvt(v.y);
            As[ak + 2][ar] = tf32cvt(v.z);
            As[ak + 3][ar] = tf32cvt(v.w);
        }
        // --- B tile 16 x 128 (k-major, tf32) ---
        if (BMODE == 0) {
#pragma unroll
            for (int h = 0; h < 2; h++) {
                const long long k = k0 + bk + h * 8;
                const float4 v = *(const float4*)(B + k * (long long)Bstride + bn0 + bnc);
                uint4 u = make_uint4(tf32cvt(v.x), tf32cvt(v.y),
                                     tf32cvt(v.z), tf32cvt(v.w));
                *(uint4*)&Bs[bk + h * 8][bnc] = u;
            }
        } else {
#pragma unroll
            for (int h = 0; h < 2; h++) {
                const float4 v = *(const float4*)(B + (long long)(bn0 + b1n) * K
                                                    + k0 + b1k + h * 4);
                Bs[b1k + h * 4 + 0][b1n] = tf32cvt(v.x);
                Bs[b1k + h * 4 + 1][b1n] = tf32cvt(v.y);
                Bs[b1k + h * 4 + 2][b1n] = tf32cvt(v.z);
                Bs[b1k + h * 4 + 3][b1n] = tf32cvt(v.w);
            }
        }
        __syncthreads();

#pragma unroll
        for (int k8 = 0; k8 < 16; k8 += 8) {
            unsigned af[2][4];
#pragma unroll
            for (int mt = 0; mt < 2; mt++) {
                const int r = wm * 32 + mt * 16 + grp;
                af[mt][0] = As[k8 + tig    ][r];
                af[mt][1] = As[k8 + tig    ][r + 8];
                af[mt][2] = As[k8 + tig + 4][r];
                af[mt][3] = As[k8 + tig + 4][r + 8];
            }
            unsigned bf[4][2];
#pragma unroll
            for (int nt = 0; nt < 4; nt++) {
                const int n = wn * 32 + nt * 8 + grp;
                bf[nt][0] = Bs[k8 + tig    ][n];
                bf[nt][1] = Bs[k8 + tig + 4][n];
            }
#pragma unroll
            for (int mt = 0; mt < 2; mt++)
#pragma unroll
                for (int nt = 0; nt < 4; nt++)
                    asm volatile(
                        "mma.sync.aligned.m16n8k8.row.col.f32.tf32.tf32.f32 "
                        "{%0,%1,%2,%3}, {%4,%5,%6,%7}, {%8,%9}, {%0,%1,%2,%3};"
                        : "+f"(acc[mt][nt][0]), "+f"(acc[mt][nt][1]),
                          "+f"(acc[mt][nt][2]), "+f"(acc[mt][nt][3])
                        : "r"(af[mt][0]), "r"(af[mt][1]),
                          "r"(af[mt][2]), "r"(af[mt][3]),
                          "r"(bf[nt][0]), "r"(bf[nt][1]));
        }
        __syncthreads();
    }

    // --- epilogue: c0,c1 -> row grp; c2,c3 -> row grp+8; cols 2*tig,2*tig+1 ---
#pragma unroll
    for (int mt = 0; mt < 2; mt++) {
#pragma unroll
        for (int half = 0; half < 2; half++) {
            const long long m = bm + wm * 32 + mt * 16 + grp + half * 8;
            float rs = 1.f;
            if (EPI == 0 && rowscale != nullptr)
                rs = basescale * __ldg(rowscale + m);
#pragma unroll
            for (int nt = 0; nt < 4; nt++) {
                const long long n = bn0 + wn * 32 + nt * 8 + 2 * tig;
                float v0 = acc[mt][nt][half * 2 + 0];
                float v1 = acc[mt][nt][half * 2 + 1];
                if (bias != nullptr) {
                    v0 += __ldg(bias + n);
                    v1 += __ldg(bias + n + 1);
                }
                if (EPI == 0) {
                    C[m * N + n]     = v0 * rs;
                    C[m * N + n + 1] = v1 * rs;
                } else {
                    const long long f = m * 512 + n;
                    C[f]     = __ldg(cur_r + f)     + 0.1f * v0;
                    C[f + 1] = __ldg(cur_r + f + 1) + 0.1f * v1;
                }
            }
        }
    }
}

// ---------------------------------------------------------------------------
// Warp-specialized streaming attention (unchanged from R9, passing).
// ---------------------------------------------------------------------------
__global__ __launch_bounds__(256)
void attn_f(const float* __restrict__ hr, const float* __restrict__ hi)
{
    __shared__ __align__(16) float shQ[DIM2];
    __shared__ __align__(16) float shAcc[8][8][32][4];
    __shared__ float shM[8], shL[8];

    const int bt = blockIdx.x;
    const int w  = threadIdx.x >> 5;
    const int c  = threadIdx.x & 31;

    {
        const float* q = g_Qk + (size_t)bt * DIM2;
        *(float4*)&shQ[threadIdx.x * 4] = *(const float4*)(q + threadIdx.x * 4);
    }
    __syncthreads();

    const float* pr = hr + (size_t)bt * (SLOTS * 512) + 4 * c;
    const float* pi = hi + (size_t)bt * (SLOTS * 512) + 4 * c;

    float m = -1e30f, l = 0.f;
    float4 acc[8];
#pragma unroll
    for (int k = 0; k < 8; k++) acc[k] = make_float4(0.f, 0.f, 0.f, 0.f);

#pragma unroll
    for (int si = 0; si < 4; si++) {
        const int s = w + si * 8;
        float4 h[8];
#pragma unroll
        for (int k = 0; k < 4; k++)
            h[k] = *(const float4*)(pr + (size_t)s * 512 + k * 128);
#pragma unroll
        for (int k = 0; k < 4; k++)
            h[k + 4] = *(const float4*)(pi + (size_t)s * 512 + k * 128);

        float p = 0.f;
#pragma unroll
        for (int k = 0; k < 8; k++) {
            const float4 q = *(const float4*)&shQ[k * 128 + 4 * c];
            p += h[k].x * q.x + h[k].y * q.y + h[k].z * q.z + h[k].w * q.w;
        }
#pragma unroll
        for (int off = 16; off; off >>= 1)
            p += __shfl_xor_sync(0xffffffffu, p, off);

        const float mn = fmaxf(m, p);
        const float cf = __expf(m - mn);
        const float pw = __expf(p - mn);
        l = l * cf + pw;
#pragma unroll
        for (int k = 0; k < 8; k++) {
            acc[k].x = acc[k].x * cf + pw * h[k].x;
            acc[k].y = acc[k].y * cf + pw * h[k].y;
            acc[k].z = acc[k].z * cf + pw * h[k].z;
            acc[k].w = acc[k].w * cf + pw * h[k].w;
        }
        m = mn;
    }

    if (c == 0) { shM[w] = m; shL[w] = l; }
    __syncthreads();
    float M = -1e30f;
#pragma unroll
    for (int i = 0; i < 8; i++) M = fmaxf(M, shM[i]);
    float L = 0.f;
#pragma unroll
    for (int i = 0; i < 8; i++) L += shL[i] * __expf(shM[i] - M);
    const float myE = __expf(m - M);

#pragma unroll
    for (int k = 0; k < 8; k++) {
        float4 v = acc[k];
        v.x *= myE; v.y *= myE; v.z *= myE; v.w *= myE;
        *(float4*)&shAcc[w][k][c][0] = v;
    }
    __syncthreads();

    const float invL = 1.f / L;
    float4 sum = make_float4(0.f, 0.f, 0.f, 0.f);
#pragma unroll
    for (int sw = 0; sw < 8; sw++) {
        const float4 v = *(const float4*)&shAcc[sw][w][c][0];
        sum.x += v.x; sum.y += v.y; sum.z += v.z; sum.w += v.w;
    }
    sum.x *= invL; sum.y *= invL; sum.z *= invL; sum.w *= invL;
    *(float4*)&g_wH[(size_t)bt * DIM2 + w * 128 + 4 * c] = sum;
}

// ---------------------------------------------------------------------------
// Host-side staged diagnostics (only on the non-captured correctness call).
// ---------------------------------------------------------------------------
static bool kl_capturing()
{
    cudaStreamCaptureStatus st = cudaStreamCaptureStatusNone;
    cudaError_t e = cudaStreamIsCapturing((cudaStream_t)0, &st);
    if (e != cudaSuccess) { (void)cudaGetLastError(); return true; }
    return st != cudaStreamCaptureStatusNone;
}
static cudaError_t kl_poll()
{
    cudaEvent_t ev;
    if (cudaEventCreateWithFlags(&ev, cudaEventDisableTiming) != cudaSuccess)
        return cudaGetLastError();
    cudaEventRecord(ev, (cudaStream_t)0);
    cudaError_t e;
    do { e = cudaEventQuery(ev); } while (e == cudaErrorNotReady);
    cudaEventDestroy(ev);
    return e;
}
static void kl_stage(bool diag, const char* name, bool* dead)
{
    if (!diag || *dead) return;
    cudaError_t e = kl_poll();
    if (e != cudaSuccess) {
        fprintf(stderr, "[KLDIAG] stage %s -> %s\n", name, cudaGetErrorString(e));
        *dead = true;
    }
}

// ---------------------------------------------------------------------------
extern "C" void kernel_launch(void* const* d_in, const int* in_sizes, int n_in,
                              void* d_out, int out_size)
{
    const bool diag = !kl_capturing();
    if (n_in < 11) return;

    // Confirmed insertion order, all fp32:
    // 0=hist_real 1=hist_imag 2=cur_r 3=cur_i 4=conf 5=qW 6=qb 7=kW 8=kb 9=vW 10=vb
    const float* hr   = (const float*)d_in[0];
    const float* hi   = (const float*)d_in[1];
    const float* cr   = (const float*)d_in[2];
    const float* ci   = (const float*)d_in[3];
    const float* conf = (const float*)d_in[4];
    const float* qW   = (const float*)d_in[5];
    const float* qb   = (const float*)d_in[6];
    const float* kW   = (const float*)d_in[7];
    // d_in[8] = kb: softmax-invariant, unused
    const float* vW   = (const float*)d_in[9];
    const float* vb   = (const float*)d_in[10];
    float* out = (float*)d_out;   // out_size=2097152 fp32 = real part

    const float scale = 0.044194173824159216f;   // 512^-0.5
    bool dead = false;

    // 1) Q = concat(cur_r,cur_i) @ qW + qb -> g_Q        [4096,512], K=1024
    gemm_t<1, 0, 0, 0><<<dim3(DIM / 128, BT / 64), 256>>>(
        cr, ci, qW, DIM, qb, nullptr, 1.f, nullptr, nullptr, BT, DIM, DIM2);
    kl_stage(diag, "gemm1", &dead);
    if (dead) return;

    // 2) Qk' = (Q @ kW^T) * scale * conf[row] -> g_Qk    [4096,1024], K=512
    gemm_t<2, 1, 0, 1><<<dim3(DIM2 / 128, BT / 64), 256>>>(
        nullptr, nullptr, kW, 0, nullptr, conf, scale, nullptr, nullptr,
        BT, DIM2, DIM);
    kl_stage(diag, "gemm2", &dead);
    if (dead) return;

    // 3) warp-specialized online-softmax stream -> g_wH
    attn_f<<<BT, 256>>>(hr, hi);
    kl_stage(diag, "attn", &dead);
    if (dead) return;

    // 4) out = cur_r + 0.1 * (wH @ vW[:,0:512] + vb[0:512])   (real part)
    gemm_t<3, 0, 1, 2><<<dim3(DIM / 128, BT / 64), 256>>>(
        nullptr, nullptr, vW, DIM2, vb, nullptr, 1.f, cr, out, BT, DIM, DIM2);
    kl_stage(diag, "gemm4", &dead);
}